// round 3
// baseline (speedup 1.0000x reference)
#include <cuda_runtime.h>
#include <cuda_bf16.h>
#include <cstdint>

// Problem constants
#define NUM_NODES 50000
#define NUM_EDGES 800000
#define D_IN  128
#define D_HID 128
#define D_OUT 40

// Scratch buffers (device globals; no allocation allowed)
__device__ float g_bufHW[NUM_NODES * D_HID];   // projected features h@W
__device__ float g_bufAGG[NUM_NODES * D_HID];  // aggregation target
__device__ int   g_is64;                       // edge_index dtype flag

// ---------------------------------------------------------------------------
// Detect whether edge_index is int64 (odd 32-bit words all zero) or int32.
// Values are in [0, 50000), so for int64 every high word is 0; for int32 the
// probability 256 consecutive random values are all 0 is ~0.
// ---------------------------------------------------------------------------
__global__ void detect_idx_dtype(const int* __restrict__ ei32) {
    if (threadIdx.x == 0 && blockIdx.x == 0) {
        int is64 = 1;
        #pragma unroll 8
        for (int i = 0; i < 256; i++) {
            if (ei32[2 * i + 1] != 0) { is64 = 0; break; }
        }
        g_is64 = is64;
    }
}

// ---------------------------------------------------------------------------
// init buffer with broadcast bias: buf[n*M + j] = b[j]
// ---------------------------------------------------------------------------
template <int M>
__global__ void init_bias_kernel(float* __restrict__ buf, const float* __restrict__ b, int total) {
    int i = blockIdx.x * blockDim.x + threadIdx.x;
    if (i < total) buf[i] = b[i % M];
}

// ---------------------------------------------------------------------------
// GEMM: C[N,128] = act(A[N,128]) @ W[128,128], act = optional relu
// Block: 256 threads, 64 rows x 128 cols tile.
// Each warp owns 8 rows; each lane owns 4 cols. acc[8][4] register tile.
// smem: W full (64KB) + A tile (32KB) = 96KB dynamic.
// ---------------------------------------------------------------------------
template <bool RELU>
__global__ void gemm128_kernel(const float* __restrict__ A, const float* __restrict__ W,
                               float* __restrict__ C, int N) {
    extern __shared__ float sm[];
    float* Ws = sm;              // 128*128
    float* As = sm + 128 * 128;  // 64*128

    const int tid = threadIdx.x;

    // Load W (4096 float4, 256 threads -> 16 each)
    {
        const float4* W4 = (const float4*)W;
        float4* Ws4 = (float4*)Ws;
        #pragma unroll
        for (int i = 0; i < 16; i++) Ws4[tid + i * 256] = W4[tid + i * 256];
    }
    // Load A tile (64 rows x 32 float4 = 2048 float4, 8 each)
    const int rowBase = blockIdx.x * 64;
    {
        const float4* A4 = (const float4*)A;
        float4* As4 = (float4*)As;
        #pragma unroll
        for (int i = 0; i < 8; i++) {
            int idx = tid + i * 256;      // 0..2047
            int r = idx >> 5;             // row within tile
            int c4 = idx & 31;            // float4 col
            float4 v;
            if (rowBase + r < N) {
                v = A4[(size_t)(rowBase + r) * 32 + c4];
                if (RELU) {
                    v.x = fmaxf(v.x, 0.f); v.y = fmaxf(v.y, 0.f);
                    v.z = fmaxf(v.z, 0.f); v.w = fmaxf(v.w, 0.f);
                }
            } else {
                v = make_float4(0.f, 0.f, 0.f, 0.f);
            }
            As4[idx] = v;
        }
    }
    __syncthreads();

    const int lane = tid & 31;
    const int warp = tid >> 5;

    float acc[8][4];
    #pragma unroll
    for (int r = 0; r < 8; r++)
        #pragma unroll
        for (int c = 0; c < 4; c++) acc[r][c] = 0.f;

    for (int k = 0; k < 128; k += 4) {
        float4 a[8];
        #pragma unroll
        for (int r = 0; r < 8; r++)
            a[r] = *(const float4*)(As + (warp * 8 + r) * 128 + k);
        float4 w[4];
        #pragma unroll
        for (int kk = 0; kk < 4; kk++)
            w[kk] = *(const float4*)(Ws + (k + kk) * 128 + lane * 4);

        #pragma unroll
        for (int kk = 0; kk < 4; kk++) {
            float4 wv = w[kk];
            #pragma unroll
            for (int r = 0; r < 8; r++) {
                float av = (kk == 0) ? a[r].x : (kk == 1) ? a[r].y : (kk == 2) ? a[r].z : a[r].w;
                acc[r][0] += av * wv.x;
                acc[r][1] += av * wv.y;
                acc[r][2] += av * wv.z;
                acc[r][3] += av * wv.w;
            }
        }
    }

    #pragma unroll
    for (int r = 0; r < 8; r++) {
        int row = rowBase + warp * 8 + r;
        if (row < N) {
            float4 o = make_float4(acc[r][0], acc[r][1], acc[r][2], acc[r][3]);
            *(float4*)(C + (size_t)row * 128 + lane * 4) = o;
        }
    }
}

// ---------------------------------------------------------------------------
// GEMM: C[N,40] = relu(A[N,128]) @ W[128,40]
// One thread per row; W staged in smem (broadcast LDS).
// ---------------------------------------------------------------------------
__global__ void gemm40_kernel(const float* __restrict__ A, const float* __restrict__ W,
                              float* __restrict__ C, int N) {
    __shared__ float Ws[128 * 40];
    for (int i = threadIdx.x; i < 128 * 40; i += blockDim.x) Ws[i] = W[i];
    __syncthreads();

    int row = blockIdx.x * blockDim.x + threadIdx.x;
    if (row >= N) return;

    float acc[40];
    #pragma unroll
    for (int j = 0; j < 40; j++) acc[j] = 0.f;

    const float4* Arow = (const float4*)(A + (size_t)row * 128);
    #pragma unroll 2
    for (int k4 = 0; k4 < 32; k4++) {
        float4 a = Arow[k4];
        a.x = fmaxf(a.x, 0.f); a.y = fmaxf(a.y, 0.f);
        a.z = fmaxf(a.z, 0.f); a.w = fmaxf(a.w, 0.f);
        #pragma unroll
        for (int kk = 0; kk < 4; kk++) {
            float av = (kk == 0) ? a.x : (kk == 1) ? a.y : (kk == 2) ? a.z : a.w;
            const float4* wrow = (const float4*)(Ws + (k4 * 4 + kk) * 40);
            #pragma unroll
            for (int j = 0; j < 10; j++) {
                float4 w = wrow[j];
                acc[j * 4 + 0] += av * w.x;
                acc[j * 4 + 1] += av * w.y;
                acc[j * 4 + 2] += av * w.z;
                acc[j * 4 + 3] += av * w.w;
            }
        }
    }

    float4* Crow = (float4*)(C + (size_t)row * 40);
    #pragma unroll
    for (int j = 0; j < 10; j++)
        Crow[j] = make_float4(acc[j * 4 + 0], acc[j * 4 + 1], acc[j * 4 + 2], acc[j * 4 + 3]);
}

// ---------------------------------------------------------------------------
// Edge scatter: agg[dst] += hw[src]  (M = M4*4 feature dims)
// One thread per (edge, float4-column). red.global.add.v4.f32 (no return).
// ---------------------------------------------------------------------------
template <int M4>
__global__ void scatter_kernel(const float* __restrict__ hw, const void* __restrict__ ei,
                               float* __restrict__ agg, int E) {
    const int M = M4 * 4;
    int i = blockIdx.x * blockDim.x + threadIdx.x;
    int e = i / M4;
    if (e >= E) return;
    int j = i - e * M4;

    int s, d;
    if (g_is64) {
        const long long* e64 = (const long long*)ei;
        s = (int)e64[e];
        d = (int)e64[E + e];
    } else {
        const int* e32 = (const int*)ei;
        s = e32[e];
        d = e32[E + e];
    }

    float4 v = *(const float4*)(hw + (size_t)s * M + j * 4);
    float* p = agg + (size_t)d * M + j * 4;
    asm volatile("red.global.add.v4.f32 [%0], {%1, %2, %3, %4};"
                 :: "l"(p), "f"(v.x), "f"(v.y), "f"(v.z), "f"(v.w)
                 : "memory");
}

// ---------------------------------------------------------------------------
// Launch
// ---------------------------------------------------------------------------
extern "C" void kernel_launch(void* const* d_in, const int* in_sizes, int n_in,
                              void* d_out, int out_size) {
    const float* x  = (const float*)d_in[0];
    const void*  ei = d_in[1];
    const float* W0 = (const float*)d_in[2];
    const float* b0 = (const float*)d_in[3];
    const float* W1 = (const float*)d_in[4];
    const float* b1 = (const float*)d_in[5];
    const float* W2 = (const float*)d_in[6];
    const float* b2 = (const float*)d_in[7];
    float* out = (float*)d_out;

    const int N = NUM_NODES, E = NUM_EDGES;

    float *bufHW, *bufAGG;
    cudaGetSymbolAddress((void**)&bufHW, g_bufHW);
    cudaGetSymbolAddress((void**)&bufAGG, g_bufAGG);

    const int SMEM = (128 * 128 + 64 * 128) * sizeof(float);  // 96KB
    cudaFuncSetAttribute(gemm128_kernel<false>, cudaFuncAttributeMaxDynamicSharedMemorySize, SMEM);
    cudaFuncSetAttribute(gemm128_kernel<true>,  cudaFuncAttributeMaxDynamicSharedMemorySize, SMEM);

    detect_idx_dtype<<<1, 32>>>((const int*)ei);

    // Layer 0: hw = x @ W0 ; agg = b0 ; agg += scatter(hw)
    gemm128_kernel<false><<<(N + 63) / 64, 256, SMEM>>>(x, W0, bufHW, N);
    init_bias_kernel<128><<<(N * 128 + 255) / 256, 256>>>(bufAGG, b0, N * 128);
    scatter_kernel<32><<<(E * 32 + 255) / 256, 256>>>(bufHW, ei, bufAGG, E);

    // Layer 1: hw = relu(agg) @ W1 ; agg = b1 ; agg += scatter(hw)
    gemm128_kernel<true><<<(N + 63) / 64, 256, SMEM>>>(bufAGG, W1, bufHW, N);
    init_bias_kernel<128><<<(N * 128 + 255) / 256, 256>>>(bufAGG, b1, N * 128);
    scatter_kernel<32><<<(E * 32 + 255) / 256, 256>>>(bufHW, ei, bufAGG, E);

    // Layer 2: hw2 = relu(agg) @ W2 ; out = b2 ; out += scatter(hw2)
    gemm40_kernel<<<(N + 255) / 256, 256>>>(bufAGG, W2, bufHW, N);
    init_bias_kernel<40><<<(N * 40 + 255) / 256, 256>>>(out, b2, N * 40);
    scatter_kernel<10><<<(E * 10 + 255) / 256, 256>>>(bufHW, ei, out, E);
}

// round 4
// speedup vs baseline: 1.3412x; 1.3412x over previous
#include <cuda_runtime.h>
#include <cuda_bf16.h>
#include <cstdint>

// Problem constants
#define NUM_NODES 50000
#define NUM_EDGES 800000
#define D_IN  128
#define D_HID 128
#define D_OUT 40

// Scratch buffers (device globals; no allocation allowed)
__device__ float g_bufHW[NUM_NODES * D_HID];   // projected features h@W
__device__ float g_bufAGG[NUM_NODES * D_HID];  // aggregation target
__device__ int   g_is64;                       // edge_index dtype flag
__device__ int   g_deg[NUM_NODES];             // degree counts, then fill cursor
__device__ int   g_off[NUM_NODES + 1];         // CSR row offsets (by dst)
__device__ int   g_csrc[NUM_EDGES];            // CSR source ids

// ---------------------------------------------------------------------------
// f32x2 packed-FMA helpers (Blackwell dual-FP32 pipe, PTX-only)
// ---------------------------------------------------------------------------
__device__ __forceinline__ unsigned long long pack2(float x, float y) {
    unsigned long long r;
    asm("mov.b64 %0, {%1, %2};" : "=l"(r) : "f"(x), "f"(y));
    return r;
}
__device__ __forceinline__ void unpack2(float& x, float& y, unsigned long long v) {
    asm("mov.b64 {%0, %1}, %2;" : "=f"(x), "=f"(y) : "l"(v));
}
#define FMA2(d, a, b) \
    asm("fma.rn.f32x2 %0, %1, %2, %0;" : "+l"(d) : "l"(a), "l"(b))

// ---------------------------------------------------------------------------
// Detect whether edge_index is int64 (odd 32-bit words all zero) or int32.
// ---------------------------------------------------------------------------
__global__ void detect_idx_dtype(const int* __restrict__ ei32) {
    if (threadIdx.x == 0 && blockIdx.x == 0) {
        int is64 = 1;
        for (int i = 0; i < 256; i++) {
            if (ei32[2 * i + 1] != 0) { is64 = 0; break; }
        }
        g_is64 = is64;
    }
}

// ---------------------------------------------------------------------------
// CSR build: zero degrees -> histogram(dst) -> scan -> copy cursor -> fill
// ---------------------------------------------------------------------------
__global__ void zero_deg_kernel() {
    int i = blockIdx.x * blockDim.x + threadIdx.x;
    if (i < NUM_NODES) g_deg[i] = 0;
}

__global__ void hist_kernel(const int* __restrict__ ei32, int E) {
    int e = blockIdx.x * blockDim.x + threadIdx.x;
    if (e >= E) return;
    int d = g_is64 ? ei32[2 * (E + e)] : ei32[E + e];
    atomicAdd(&g_deg[d], 1);
}

// Single-block exclusive scan over g_deg -> g_off (1024 threads).
__global__ void scan_kernel() {
    __shared__ int wsum[32];
    __shared__ int carry_s;
    const int tid = threadIdx.x;
    const int lane = tid & 31, wid = tid >> 5;
    if (tid == 0) carry_s = 0;
    __syncthreads();
    for (int base = 0; base < NUM_NODES; base += 1024) {
        int i = base + tid;
        int v = (i < NUM_NODES) ? g_deg[i] : 0;
        int x = v;
        #pragma unroll
        for (int s = 1; s < 32; s <<= 1) {
            int t = __shfl_up_sync(0xffffffffu, x, s);
            if (lane >= s) x += t;
        }
        if (lane == 31) wsum[wid] = x;
        __syncthreads();
        if (wid == 0) {
            int y = wsum[lane];
            #pragma unroll
            for (int s = 1; s < 32; s <<= 1) {
                int t = __shfl_up_sync(0xffffffffu, y, s);
                if (lane >= s) y += t;
            }
            wsum[lane] = y;
        }
        __syncthreads();
        int warpoff = (wid == 0) ? 0 : wsum[wid - 1];
        int incl = carry_s + warpoff + x;
        if (i < NUM_NODES) g_off[i] = incl - v;  // exclusive
        __syncthreads();
        if (tid == 1023) carry_s = incl;
        __syncthreads();
    }
    if (tid == 0) g_off[NUM_NODES] = carry_s;
}

__global__ void copy_cursor_kernel() {
    int i = blockIdx.x * blockDim.x + threadIdx.x;
    if (i < NUM_NODES) g_deg[i] = g_off[i];   // reuse g_deg as cursor
}

__global__ void fill_kernel(const int* __restrict__ ei32, int E) {
    int e = blockIdx.x * blockDim.x + threadIdx.x;
    if (e >= E) return;
    int s, d;
    if (g_is64) { s = ei32[2 * e]; d = ei32[2 * (E + e)]; }
    else        { s = ei32[e];     d = ei32[E + e]; }
    int pos = atomicAdd(&g_deg[d], 1);
    g_csrc[pos] = s;
}

// ---------------------------------------------------------------------------
// GEMM: C[N,128] = act(A[N,128]) @ W[128,128]  — f32x2 packed FMA
// Block 256 threads, 64-row tile. Warp = 8 rows, lane = 4 cols (2 u64 pairs).
// ---------------------------------------------------------------------------
template <bool RELU>
__global__ void gemm128_kernel(const float* __restrict__ A, const float* __restrict__ W,
                               float* __restrict__ C, int N) {
    extern __shared__ float sm[];
    float* Ws = sm;              // 128*128
    float* As = sm + 128 * 128;  // 64*128

    const int tid = threadIdx.x;

    // Load W (4096 float4)
    {
        const float4* W4 = (const float4*)W;
        float4* Ws4 = (float4*)Ws;
        #pragma unroll
        for (int i = 0; i < 16; i++) Ws4[tid + i * 256] = W4[tid + i * 256];
    }
    // Load A tile (64 rows x 32 float4)
    const int rowBase = blockIdx.x * 64;
    {
        const float4* A4 = (const float4*)A;
        float4* As4 = (float4*)As;
        #pragma unroll
        for (int i = 0; i < 8; i++) {
            int idx = tid + i * 256;
            int r = idx >> 5;
            int c4 = idx & 31;
            float4 v;
            if (rowBase + r < N) {
                v = A4[(size_t)(rowBase + r) * 32 + c4];
                if (RELU) {
                    v.x = fmaxf(v.x, 0.f); v.y = fmaxf(v.y, 0.f);
                    v.z = fmaxf(v.z, 0.f); v.w = fmaxf(v.w, 0.f);
                }
            } else {
                v = make_float4(0.f, 0.f, 0.f, 0.f);
            }
            As4[idx] = v;
        }
    }
    __syncthreads();

    const int lane = tid & 31;
    const int warp = tid >> 5;

    unsigned long long acc2[8][2];
    #pragma unroll
    for (int r = 0; r < 8; r++) { acc2[r][0] = 0ull; acc2[r][1] = 0ull; }

    for (int k = 0; k < 128; k += 4) {
        float4 a[8];
        #pragma unroll
        for (int r = 0; r < 8; r++)
            a[r] = *(const float4*)(As + (warp * 8 + r) * 128 + k);

        unsigned long long wlo[4], whi[4];
        #pragma unroll
        for (int kk = 0; kk < 4; kk++) {
            const unsigned long long* wp =
                (const unsigned long long*)(Ws + (k + kk) * 128 + lane * 4);
            wlo[kk] = wp[0];
            whi[kk] = wp[1];
        }

        #pragma unroll
        for (int kk = 0; kk < 4; kk++) {
            #pragma unroll
            for (int r = 0; r < 8; r++) {
                float av = (kk == 0) ? a[r].x : (kk == 1) ? a[r].y
                         : (kk == 2) ? a[r].z : a[r].w;
                unsigned long long av2 = pack2(av, av);
                FMA2(acc2[r][0], av2, wlo[kk]);
                FMA2(acc2[r][1], av2, whi[kk]);
            }
        }
    }

    #pragma unroll
    for (int r = 0; r < 8; r++) {
        int row = rowBase + warp * 8 + r;
        if (row < N) {
            float4 o;
            unpack2(o.x, o.y, acc2[r][0]);
            unpack2(o.z, o.w, acc2[r][1]);
            *(float4*)(C + (size_t)row * 128 + lane * 4) = o;
        }
    }
}

// ---------------------------------------------------------------------------
// GEMM: C[N,40] = relu(A[N,128]) @ W[128,40] — f32x2, one row per thread.
// ---------------------------------------------------------------------------
__global__ void gemm40_kernel(const float* __restrict__ A, const float* __restrict__ W,
                              float* __restrict__ C, int N) {
    __shared__ float Ws[128 * 40];
    for (int i = threadIdx.x; i < 128 * 40; i += blockDim.x) Ws[i] = W[i];
    __syncthreads();

    int row = blockIdx.x * blockDim.x + threadIdx.x;
    if (row >= N) return;

    unsigned long long acc2[20];
    #pragma unroll
    for (int j = 0; j < 20; j++) acc2[j] = 0ull;

    const float4* Arow = (const float4*)(A + (size_t)row * 128);
    for (int k4 = 0; k4 < 32; k4++) {
        float4 a = Arow[k4];
        a.x = fmaxf(a.x, 0.f); a.y = fmaxf(a.y, 0.f);
        a.z = fmaxf(a.z, 0.f); a.w = fmaxf(a.w, 0.f);
        #pragma unroll
        for (int kk = 0; kk < 4; kk++) {
            float av = (kk == 0) ? a.x : (kk == 1) ? a.y : (kk == 2) ? a.z : a.w;
            unsigned long long av2 = pack2(av, av);
            const unsigned long long* wrow =
                (const unsigned long long*)(Ws + (k4 * 4 + kk) * 40);
            #pragma unroll
            for (int j = 0; j < 20; j++) FMA2(acc2[j], av2, wrow[j]);
        }
    }

    unsigned long long* Co = (unsigned long long*)(C + (size_t)row * 40);
    #pragma unroll
    for (int j = 0; j < 20; j++) Co[j] = acc2[j];
}

// ---------------------------------------------------------------------------
// CSR gather (128 dims): one warp per node, lane owns 4 cols.
// agg[n] = b + sum_{e in csr[n]} hw[src[e]]   (bias init fused)
// ---------------------------------------------------------------------------
__global__ void gather128_kernel(const float* __restrict__ hw,
                                 const float* __restrict__ b,
                                 float* __restrict__ agg) {
    int w = (blockIdx.x * blockDim.x + threadIdx.x) >> 5;
    int lane = threadIdx.x & 31;
    if (w >= NUM_NODES) return;
    int beg = __ldg(&g_off[w]);
    int end = __ldg(&g_off[w + 1]);

    float4 acc = *(const float4*)(b + lane * 4);
    int i = beg;
    for (; i + 4 <= end; i += 4) {
        int s0 = g_csrc[i], s1 = g_csrc[i + 1], s2 = g_csrc[i + 2], s3 = g_csrc[i + 3];
        float4 v0 = *(const float4*)(hw + (size_t)s0 * 128 + lane * 4);
        float4 v1 = *(const float4*)(hw + (size_t)s1 * 128 + lane * 4);
        float4 v2 = *(const float4*)(hw + (size_t)s2 * 128 + lane * 4);
        float4 v3 = *(const float4*)(hw + (size_t)s3 * 128 + lane * 4);
        acc.x += v0.x + v1.x + v2.x + v3.x;
        acc.y += v0.y + v1.y + v2.y + v3.y;
        acc.z += v0.z + v1.z + v2.z + v3.z;
        acc.w += v0.w + v1.w + v2.w + v3.w;
    }
    for (; i < end; i++) {
        int s = g_csrc[i];
        float4 v = *(const float4*)(hw + (size_t)s * 128 + lane * 4);
        acc.x += v.x; acc.y += v.y; acc.z += v.z; acc.w += v.w;
    }
    *(float4*)(agg + (size_t)w * 128 + lane * 4) = acc;
}

// ---------------------------------------------------------------------------
// CSR gather (40 dims): one warp per node, lanes 0..9 own a float4 each.
// ---------------------------------------------------------------------------
__global__ void gather40_kernel(const float* __restrict__ hw,
                                const float* __restrict__ b,
                                float* __restrict__ out) {
    int w = (blockIdx.x * blockDim.x + threadIdx.x) >> 5;
    int lane = threadIdx.x & 31;
    if (w >= NUM_NODES) return;
    int beg = __ldg(&g_off[w]);
    int end = __ldg(&g_off[w + 1]);

    float4 acc = make_float4(0.f, 0.f, 0.f, 0.f);
    if (lane < 10) acc = *(const float4*)(b + lane * 4);
    int i = beg;
    for (; i + 2 <= end; i += 2) {
        int s0 = g_csrc[i], s1 = g_csrc[i + 1];
        if (lane < 10) {
            float4 v0 = *(const float4*)(hw + (size_t)s0 * 40 + lane * 4);
            float4 v1 = *(const float4*)(hw + (size_t)s1 * 40 + lane * 4);
            acc.x += v0.x + v1.x; acc.y += v0.y + v1.y;
            acc.z += v0.z + v1.z; acc.w += v0.w + v1.w;
        }
    }
    for (; i < end; i++) {
        int s = g_csrc[i];
        if (lane < 10) {
            float4 v = *(const float4*)(hw + (size_t)s * 40 + lane * 4);
            acc.x += v.x; acc.y += v.y; acc.z += v.z; acc.w += v.w;
        }
    }
    if (lane < 10)
        *(float4*)(out + (size_t)w * 40 + lane * 4) = acc;
}

// ---------------------------------------------------------------------------
// Launch
// ---------------------------------------------------------------------------
extern "C" void kernel_launch(void* const* d_in, const int* in_sizes, int n_in,
                              void* d_out, int out_size) {
    const float* x  = (const float*)d_in[0];
    const int*   ei = (const int*)d_in[1];
    const float* W0 = (const float*)d_in[2];
    const float* b0 = (const float*)d_in[3];
    const float* W1 = (const float*)d_in[4];
    const float* b1 = (const float*)d_in[5];
    const float* W2 = (const float*)d_in[6];
    const float* b2 = (const float*)d_in[7];
    float* out = (float*)d_out;

    const int N = NUM_NODES, E = NUM_EDGES;

    float *bufHW, *bufAGG;
    cudaGetSymbolAddress((void**)&bufHW, g_bufHW);
    cudaGetSymbolAddress((void**)&bufAGG, g_bufAGG);

    const int SMEM = (128 * 128 + 64 * 128) * sizeof(float);  // 96KB
    cudaFuncSetAttribute(gemm128_kernel<false>, cudaFuncAttributeMaxDynamicSharedMemorySize, SMEM);
    cudaFuncSetAttribute(gemm128_kernel<true>,  cudaFuncAttributeMaxDynamicSharedMemorySize, SMEM);

    // --- CSR build (per launch; graph-capturable, no allocs) ---
    detect_idx_dtype<<<1, 32>>>(ei);
    zero_deg_kernel<<<(N + 255) / 256, 256>>>();
    hist_kernel<<<(E + 255) / 256, 256>>>(ei, E);
    scan_kernel<<<1, 1024>>>();
    copy_cursor_kernel<<<(N + 255) / 256, 256>>>();
    fill_kernel<<<(E + 255) / 256, 256>>>(ei, E);

    const int GWARP_BLOCKS = (N * 32 + 255) / 256;  // 1 warp per node

    // Layer 0
    gemm128_kernel<false><<<(N + 63) / 64, 256, SMEM>>>(x, W0, bufHW, N);
    gather128_kernel<<<GWARP_BLOCKS, 256>>>(bufHW, b0, bufAGG);

    // Layer 1
    gemm128_kernel<true><<<(N + 63) / 64, 256, SMEM>>>(bufAGG, W1, bufHW, N);
    gather128_kernel<<<GWARP_BLOCKS, 256>>>(bufHW, b1, bufAGG);

    // Layer 2
    gemm40_kernel<<<(N + 255) / 256, 256>>>(bufAGG, W2, bufHW, N);
    gather40_kernel<<<GWARP_BLOCKS, 256>>>(bufHW, b2, out);
}

// round 6
// speedup vs baseline: 1.5677x; 1.1688x over previous
#include <cuda_runtime.h>
#include <cuda_bf16.h>
#include <cstdint>

// Problem constants
#define NUM_NODES 50000
#define NUM_EDGES 800000
#define D_IN  128
#define D_HID 128
#define D_OUT 40

#define SCAN_BLK 512
#define SCAN_NBLOCKS ((NUM_NODES + SCAN_BLK - 1) / SCAN_BLK)   // 98

// Scratch buffers (device globals; no allocation allowed)
__device__ float g_bufHW[NUM_NODES * D_HID];   // projected features h@W
__device__ float g_bufAGG[NUM_NODES * D_HID];  // aggregation target
__device__ int   g_is64;                       // edge_index dtype flag
__device__ int   g_deg[NUM_NODES];             // degree counts, then fill cursor
__device__ int   g_off[NUM_NODES + 1];         // CSR row offsets (by dst)
__device__ int   g_csrc[NUM_EDGES];            // CSR source ids
__device__ int   g_bsum[SCAN_NBLOCKS];         // per-block scan partials

// ---------------------------------------------------------------------------
// f32x2 packed-FMA helpers (Blackwell dual-FP32 pipe, PTX-only)
// ---------------------------------------------------------------------------
__device__ __forceinline__ unsigned long long pack2(float x, float y) {
    unsigned long long r;
    asm("mov.b64 %0, {%1, %2};" : "=l"(r) : "f"(x), "f"(y));
    return r;
}
__device__ __forceinline__ void unpack2(float& x, float& y, unsigned long long v) {
    asm("mov.b64 {%0, %1}, %2;" : "=f"(x), "=f"(y) : "l"(v));
}
#define FMA2(d, a, b) \
    asm("fma.rn.f32x2 %0, %1, %2, %0;" : "+l"(d) : "l"(a), "l"(b))

// ---------------------------------------------------------------------------
// Detect whether edge_index is int64 (odd 32-bit words all zero) or int32.
// ---------------------------------------------------------------------------
__global__ void detect_idx_dtype(const int* __restrict__ ei32) {
    if (threadIdx.x == 0 && blockIdx.x == 0) {
        int is64 = 1;
        for (int i = 0; i < 256; i++) {
            if (ei32[2 * i + 1] != 0) { is64 = 0; break; }
        }
        g_is64 = is64;
    }
}

// ---------------------------------------------------------------------------
// CSR build: zero -> histogram(dst) -> 3-phase scan -> fill
// ---------------------------------------------------------------------------
__global__ void zero_deg_kernel() {
    int i = blockIdx.x * blockDim.x + threadIdx.x;
    if (i < NUM_NODES) g_deg[i] = 0;
}

__global__ void hist_kernel(const int* __restrict__ ei32, int E) {
    int e = blockIdx.x * blockDim.x + threadIdx.x;
    if (e >= E) return;
    int d = g_is64 ? ei32[2 * (E + e)] : ei32[E + e];
    atomicAdd(&g_deg[d], 1);
}

// Phase A: per-block exclusive scan (512 elems/block); write block total.
__global__ void scanA_kernel() {
    __shared__ int wsum[16];
    const int tid = threadIdx.x;
    const int lane = tid & 31, wid = tid >> 5;
    int i = blockIdx.x * SCAN_BLK + tid;
    int v = (i < NUM_NODES) ? g_deg[i] : 0;
    int x = v;
    #pragma unroll
    for (int s = 1; s < 32; s <<= 1) {
        int t = __shfl_up_sync(0xffffffffu, x, s);
        if (lane >= s) x += t;
    }
    if (lane == 31) wsum[wid] = x;
    __syncthreads();
    if (wid == 0 && lane < 16) {
        int y = wsum[lane];
        #pragma unroll
        for (int s = 1; s < 16; s <<= 1) {
            int t = __shfl_up_sync(0xffffu, y, s);
            if (lane >= s) y += t;
        }
        wsum[lane] = y;
    }
    __syncthreads();
    int warpoff = (wid == 0) ? 0 : wsum[wid - 1];
    if (i < NUM_NODES) g_off[i] = warpoff + x - v;   // exclusive within block
    if (tid == SCAN_BLK - 1) g_bsum[blockIdx.x] = wsum[15];
}

// Phase B: single block scans the 98 block totals (exclusive, in place).
__global__ void scanB_kernel() {
    __shared__ int wsum[4];
    const int tid = threadIdx.x;     // 128 threads
    const int lane = tid & 31, wid = tid >> 5;
    int v = (tid < SCAN_NBLOCKS) ? g_bsum[tid] : 0;
    int x = v;
    #pragma unroll
    for (int s = 1; s < 32; s <<= 1) {
        int t = __shfl_up_sync(0xffffffffu, x, s);
        if (lane >= s) x += t;
    }
    if (lane == 31) wsum[wid] = x;
    __syncthreads();
    if (tid == 0) {
        int c = 0;
        #pragma unroll
        for (int k = 0; k < 4; k++) { int t = wsum[k]; wsum[k] = c; c += t; }
    }
    __syncthreads();
    int excl = wsum[wid] + x - v;
    if (tid < SCAN_NBLOCKS) g_bsum[tid] = excl;
    if (tid == 127) g_off[NUM_NODES] = excl + v;     // grand total (=E)
}

// Phase C: add block offsets; also init fill cursor (g_deg = g_off).
__global__ void scanC_kernel() {
    int i = blockIdx.x * blockDim.x + threadIdx.x;
    if (i >= NUM_NODES) return;
    int o = g_off[i] + g_bsum[i / SCAN_BLK];
    g_off[i] = o;
    g_deg[i] = o;
}

__global__ void fill_kernel(const int* __restrict__ ei32, int E) {
    int e = blockIdx.x * blockDim.x + threadIdx.x;
    if (e >= E) return;
    int s, d;
    if (g_is64) { s = ei32[2 * e]; d = ei32[2 * (E + e)]; }
    else        { s = ei32[e];     d = ei32[E + e]; }
    int pos = atomicAdd(&g_deg[d], 1);
    g_csrc[pos] = s;
}

// ---------------------------------------------------------------------------
// GEMM: C[N,128] = act(A[N,128]) @ W[128,128]  — f32x2 packed FMA
// Block 256 threads, 64-row tile. Warp = 8 rows, lane = 4 cols (2 u64 pairs).
// ---------------------------------------------------------------------------
template <bool RELU>
__global__ void gemm128_kernel(const float* __restrict__ A, const float* __restrict__ W,
                               float* __restrict__ C, int N) {
    extern __shared__ float sm[];
    float* Ws = sm;              // 128*128
    float* As = sm + 128 * 128;  // 64*128

    const int tid = threadIdx.x;

    // Load W (4096 float4)
    {
        const float4* W4 = (const float4*)W;
        float4* Ws4 = (float4*)Ws;
        #pragma unroll
        for (int i = 0; i < 16; i++) Ws4[tid + i * 256] = W4[tid + i * 256];
    }
    // Load A tile (64 rows x 32 float4)
    const int rowBase = blockIdx.x * 64;
    {
        const float4* A4 = (const float4*)A;
        float4* As4 = (float4*)As;
        #pragma unroll
        for (int i = 0; i < 8; i++) {
            int idx = tid + i * 256;
            int r = idx >> 5;
            int c4 = idx & 31;
            float4 v;
            if (rowBase + r < N) {
                v = A4[(size_t)(rowBase + r) * 32 + c4];
                if (RELU) {
                    v.x = fmaxf(v.x, 0.f); v.y = fmaxf(v.y, 0.f);
                    v.z = fmaxf(v.z, 0.f); v.w = fmaxf(v.w, 0.f);
                }
            } else {
                v = make_float4(0.f, 0.f, 0.f, 0.f);
            }
            As4[idx] = v;
        }
    }
    __syncthreads();

    const int lane = tid & 31;
    const int warp = tid >> 5;

    unsigned long long acc2[8][2];
    #pragma unroll
    for (int r = 0; r < 8; r++) { acc2[r][0] = 0ull; acc2[r][1] = 0ull; }

    for (int k = 0; k < 128; k += 4) {
        float4 a[8];
        #pragma unroll
        for (int r = 0; r < 8; r++)
            a[r] = *(const float4*)(As + (warp * 8 + r) * 128 + k);

        unsigned long long wlo[4], whi[4];
        #pragma unroll
        for (int kk = 0; kk < 4; kk++) {
            const unsigned long long* wp =
                (const unsigned long long*)(Ws + (k + kk) * 128 + lane * 4);
            wlo[kk] = wp[0];
            whi[kk] = wp[1];
        }

        #pragma unroll
        for (int kk = 0; kk < 4; kk++) {
            #pragma unroll
            for (int r = 0; r < 8; r++) {
                float av = (kk == 0) ? a[r].x : (kk == 1) ? a[r].y
                         : (kk == 2) ? a[r].z : a[r].w;
                unsigned long long av2 = pack2(av, av);
                FMA2(acc2[r][0], av2, wlo[kk]);
                FMA2(acc2[r][1], av2, whi[kk]);
            }
        }
    }

    #pragma unroll
    for (int r = 0; r < 8; r++) {
        int row = rowBase + warp * 8 + r;
        if (row < N) {
            float4 o;
            unpack2(o.x, o.y, acc2[r][0]);
            unpack2(o.z, o.w, acc2[r][1]);
            *(float4*)(C + (size_t)row * 128 + lane * 4) = o;
        }
    }
}

// ---------------------------------------------------------------------------
// GEMM: C[N,40] = relu(A[N,128]) @ W[128,40] — f32x2, one row per thread.
// ---------------------------------------------------------------------------
__global__ void gemm40_kernel(const float* __restrict__ A, const float* __restrict__ W,
                              float* __restrict__ C, int N) {
    __shared__ float Ws[128 * 40];
    for (int i = threadIdx.x; i < 128 * 40; i += blockDim.x) Ws[i] = W[i];
    __syncthreads();

    int row = blockIdx.x * blockDim.x + threadIdx.x;
    if (row >= N) return;

    unsigned long long acc2[20];
    #pragma unroll
    for (int j = 0; j < 20; j++) acc2[j] = 0ull;

    const float4* Arow = (const float4*)(A + (size_t)row * 128);
    for (int k4 = 0; k4 < 32; k4++) {
        float4 a = Arow[k4];
        a.x = fmaxf(a.x, 0.f); a.y = fmaxf(a.y, 0.f);
        a.z = fmaxf(a.z, 0.f); a.w = fmaxf(a.w, 0.f);
        #pragma unroll
        for (int kk = 0; kk < 4; kk++) {
            float av = (kk == 0) ? a.x : (kk == 1) ? a.y : (kk == 2) ? a.z : a.w;
            unsigned long long av2 = pack2(av, av);
            const unsigned long long* wrow =
                (const unsigned long long*)(Ws + (k4 * 4 + kk) * 40);
            #pragma unroll
            for (int j = 0; j < 20; j++) FMA2(acc2[j], av2, wrow[j]);
        }
    }

    unsigned long long* Co = (unsigned long long*)(C + (size_t)row * 40);
    #pragma unroll
    for (int j = 0; j < 20; j++) Co[j] = acc2[j];
}

// ---------------------------------------------------------------------------
// CSR gather (128 dims): one warp per node, lane owns 4 cols.
// agg[n] = b + sum_{e in csr[n]} hw[src[e]]   (bias init fused)
// ---------------------------------------------------------------------------
__global__ void gather128_kernel(const float* __restrict__ hw,
                                 const float* __restrict__ b,
                                 float* __restrict__ agg) {
    int w = (blockIdx.x * blockDim.x + threadIdx.x) >> 5;
    int lane = threadIdx.x & 31;
    if (w >= NUM_NODES) return;
    int beg = __ldg(&g_off[w]);
    int end = __ldg(&g_off[w + 1]);

    float4 acc = *(const float4*)(b + lane * 4);
    int i = beg;
    for (; i + 4 <= end; i += 4) {
        int s0 = g_csrc[i], s1 = g_csrc[i + 1], s2 = g_csrc[i + 2], s3 = g_csrc[i + 3];
        float4 v0 = *(const float4*)(hw + (size_t)s0 * 128 + lane * 4);
        float4 v1 = *(const float4*)(hw + (size_t)s1 * 128 + lane * 4);
        float4 v2 = *(const float4*)(hw + (size_t)s2 * 128 + lane * 4);
        float4 v3 = *(const float4*)(hw + (size_t)s3 * 128 + lane * 4);
        acc.x += v0.x + v1.x + v2.x + v3.x;
        acc.y += v0.y + v1.y + v2.y + v3.y;
        acc.z += v0.z + v1.z + v2.z + v3.z;
        acc.w += v0.w + v1.w + v2.w + v3.w;
    }
    for (; i < end; i++) {
        int s = g_csrc[i];
        float4 v = *(const float4*)(hw + (size_t)s * 128 + lane * 4);
        acc.x += v.x; acc.y += v.y; acc.z += v.z; acc.w += v.w;
    }
    *(float4*)(agg + (size_t)w * 128 + lane * 4) = acc;
}

// ---------------------------------------------------------------------------
// CSR gather (40 dims): one warp per node, lanes 0..9 own a float4 each.
// ---------------------------------------------------------------------------
__global__ void gather40_kernel(const float* __restrict__ hw,
                                const float* __restrict__ b,
                                float* __restrict__ out) {
    int w = (blockIdx.x * blockDim.x + threadIdx.x) >> 5;
    int lane = threadIdx.x & 31;
    if (w >= NUM_NODES) return;
    int beg = __ldg(&g_off[w]);
    int end = __ldg(&g_off[w + 1]);

    float4 acc = make_float4(0.f, 0.f, 0.f, 0.f);
    if (lane < 10) acc = *(const float4*)(b + lane * 4);
    int i = beg;
    for (; i + 2 <= end; i += 2) {
        int s0 = g_csrc[i], s1 = g_csrc[i + 1];
        if (lane < 10) {
            float4 v0 = *(const float4*)(hw + (size_t)s0 * 40 + lane * 4);
            float4 v1 = *(const float4*)(hw + (size_t)s1 * 40 + lane * 4);
            acc.x += v0.x + v1.x; acc.y += v0.y + v1.y;
            acc.z += v0.z + v1.z; acc.w += v0.w + v1.w;
        }
    }
    for (; i < end; i++) {
        int s = g_csrc[i];
        if (lane < 10) {
            float4 v = *(const float4*)(hw + (size_t)s * 40 + lane * 4);
            acc.x += v.x; acc.y += v.y; acc.z += v.z; acc.w += v.w;
        }
    }
    if (lane < 10)
        *(float4*)(out + (size_t)w * 40 + lane * 4) = acc;
}

// ---------------------------------------------------------------------------
// Launch
// ---------------------------------------------------------------------------
extern "C" void kernel_launch(void* const* d_in, const int* in_sizes, int n_in,
                              void* d_out, int out_size) {
    const float* x  = (const float*)d_in[0];
    const int*   ei = (const int*)d_in[1];
    const float* W0 = (const float*)d_in[2];
    const float* b0 = (const float*)d_in[3];
    const float* W1 = (const float*)d_in[4];
    const float* b1 = (const float*)d_in[5];
    const float* W2 = (const float*)d_in[6];
    const float* b2 = (const float*)d_in[7];
    float* out = (float*)d_out;

    const int N = NUM_NODES, E = NUM_EDGES;

    float *bufHW, *bufAGG;
    cudaGetSymbolAddress((void**)&bufHW, g_bufHW);
    cudaGetSymbolAddress((void**)&bufAGG, g_bufAGG);

    const int SMEM = (128 * 128 + 64 * 128) * sizeof(float);  // 96KB
    cudaFuncSetAttribute(gemm128_kernel<false>, cudaFuncAttributeMaxDynamicSharedMemorySize, SMEM);
    cudaFuncSetAttribute(gemm128_kernel<true>,  cudaFuncAttributeMaxDynamicSharedMemorySize, SMEM);

    // --- CSR build (per launch; graph-capturable, no allocs) ---
    detect_idx_dtype<<<1, 32>>>(ei);
    zero_deg_kernel<<<(N + 255) / 256, 256>>>();
    hist_kernel<<<(E + 255) / 256, 256>>>(ei, E);
    scanA_kernel<<<SCAN_NBLOCKS, SCAN_BLK>>>();
    scanB_kernel<<<1, 128>>>();
    scanC_kernel<<<(N + 255) / 256, 256>>>();
    fill_kernel<<<(E + 255) / 256, 256>>>(ei, E);

    const int GWARP_BLOCKS = (N * 32 + 255) / 256;  // 1 warp per node

    // Layer 0
    gemm128_kernel<false><<<(N + 63) / 64, 256, SMEM>>>(x, W0, bufHW, N);
    gather128_kernel<<<GWARP_BLOCKS, 256>>>(bufHW, b0, bufAGG);

    // Layer 1
    gemm128_kernel<true><<<(N + 63) / 64, 256, SMEM>>>(bufAGG, W1, bufHW, N);
    gather128_kernel<<<GWARP_BLOCKS, 256>>>(bufHW, b1, bufAGG);

    // Layer 2
    gemm40_kernel<<<(N + 255) / 256, 256>>>(bufAGG, W2, bufHW, N);
    gather40_kernel<<<GWARP_BLOCKS, 256>>>(bufHW, b2, out);
}

// round 7
// speedup vs baseline: 1.6290x; 1.0392x over previous
#include <cuda_runtime.h>
#include <cuda_bf16.h>
#include <cstdint>

// Problem constants
#define NUM_NODES 50000
#define NUM_EDGES 800000
#define D_IN  128
#define D_HID 128
#define D_OUT 40

#define SCAN_BLK 512
#define SCAN_NBLOCKS ((NUM_NODES + SCAN_BLK - 1) / SCAN_BLK)   // 98

// Scratch buffers (device globals; no allocation allowed)
__device__ float g_bufHW[NUM_NODES * D_HID];   // projected features h@W
__device__ float g_bufAGG[NUM_NODES * D_HID];  // aggregation target
__device__ int   g_is64;                       // edge_index dtype flag
__device__ int   g_deg[NUM_NODES];             // degree counts, then fill cursor
__device__ int   g_off[NUM_NODES + 1];         // CSR row offsets (by dst)
__device__ int   g_csrc[NUM_EDGES];            // CSR source ids
__device__ int   g_bsum[SCAN_NBLOCKS];         // per-block scan partials

// ---------------------------------------------------------------------------
// f32x2 packed-FMA helpers (Blackwell dual-FP32 pipe, PTX-only)
// ---------------------------------------------------------------------------
__device__ __forceinline__ unsigned long long pack2(float x, float y) {
    unsigned long long r;
    asm("mov.b64 %0, {%1, %2};" : "=l"(r) : "f"(x), "f"(y));
    return r;
}
__device__ __forceinline__ void unpack2(float& x, float& y, unsigned long long v) {
    asm("mov.b64 {%0, %1}, %2;" : "=f"(x), "=f"(y) : "l"(v));
}
#define FMA2(d, a, b) \
    asm("fma.rn.f32x2 %0, %1, %2, %0;" : "+l"(d) : "l"(a), "l"(b))

// ---------------------------------------------------------------------------
// Detect whether edge_index is int64 (odd 32-bit words all zero) or int32.
// ---------------------------------------------------------------------------
__global__ void detect_idx_dtype(const int* __restrict__ ei32) {
    if (threadIdx.x == 0 && blockIdx.x == 0) {
        int is64 = 1;
        for (int i = 0; i < 256; i++) {
            if (ei32[2 * i + 1] != 0) { is64 = 0; break; }
        }
        g_is64 = is64;
    }
}

// ---------------------------------------------------------------------------
// CSR build: zero (memset) -> histogram(dst) -> 3-phase scan -> fill
// ---------------------------------------------------------------------------
__global__ void hist_kernel(const int* __restrict__ ei32, int E) {
    int e = blockIdx.x * blockDim.x + threadIdx.x;
    if (e >= E) return;
    int d = g_is64 ? ei32[2 * (E + e)] : ei32[E + e];
    atomicAdd(&g_deg[d], 1);
}

// Phase A: per-block exclusive scan (512 elems/block); write block total.
__global__ void scanA_kernel() {
    __shared__ int wsum[16];
    const int tid = threadIdx.x;
    const int lane = tid & 31, wid = tid >> 5;
    int i = blockIdx.x * SCAN_BLK + tid;
    int v = (i < NUM_NODES) ? g_deg[i] : 0;
    int x = v;
    #pragma unroll
    for (int s = 1; s < 32; s <<= 1) {
        int t = __shfl_up_sync(0xffffffffu, x, s);
        if (lane >= s) x += t;
    }
    if (lane == 31) wsum[wid] = x;
    __syncthreads();
    if (wid == 0 && lane < 16) {
        int y = wsum[lane];
        #pragma unroll
        for (int s = 1; s < 16; s <<= 1) {
            int t = __shfl_up_sync(0xffffu, y, s);
            if (lane >= s) y += t;
        }
        wsum[lane] = y;
    }
    __syncthreads();
    int warpoff = (wid == 0) ? 0 : wsum[wid - 1];
    if (i < NUM_NODES) g_off[i] = warpoff + x - v;   // exclusive within block
    if (tid == SCAN_BLK - 1) g_bsum[blockIdx.x] = wsum[15];
}

// Phase B: single block scans the 98 block totals (exclusive, in place).
__global__ void scanB_kernel() {
    __shared__ int wsum[4];
    const int tid = threadIdx.x;     // 128 threads
    const int lane = tid & 31, wid = tid >> 5;
    int v = (tid < SCAN_NBLOCKS) ? g_bsum[tid] : 0;
    int x = v;
    #pragma unroll
    for (int s = 1; s < 32; s <<= 1) {
        int t = __shfl_up_sync(0xffffffffu, x, s);
        if (lane >= s) x += t;
    }
    if (lane == 31) wsum[wid] = x;
    __syncthreads();
    if (tid == 0) {
        int c = 0;
        #pragma unroll
        for (int k = 0; k < 4; k++) { int t = wsum[k]; wsum[k] = c; c += t; }
    }
    __syncthreads();
    int excl = wsum[wid] + x - v;
    if (tid < SCAN_NBLOCKS) g_bsum[tid] = excl;
    if (tid == 127) g_off[NUM_NODES] = excl + v;     // grand total (=E)
}

// Phase C: add block offsets; also init fill cursor (g_deg = g_off).
__global__ void scanC_kernel() {
    int i = blockIdx.x * blockDim.x + threadIdx.x;
    if (i >= NUM_NODES) return;
    int o = g_off[i] + g_bsum[i / SCAN_BLK];
    g_off[i] = o;
    g_deg[i] = o;
}

__global__ void fill_kernel(const int* __restrict__ ei32, int E) {
    int e = blockIdx.x * blockDim.x + threadIdx.x;
    if (e >= E) return;
    int s, d;
    if (g_is64) { s = ei32[2 * e]; d = ei32[2 * (E + e)]; }
    else        { s = ei32[e];     d = ei32[E + e]; }
    int pos = atomicAdd(&g_deg[d], 1);
    g_csrc[pos] = s;
}

// ---------------------------------------------------------------------------
// GEMM: C[N,128] = act(A[N,128]) @ W[128,128]  — f32x2 packed FMA
// Block 256 threads, 64-row tile. Warp = 8 rows, lane = 4 cols (2 u64 pairs).
// ---------------------------------------------------------------------------
template <bool RELU>
__global__ void gemm128_kernel(const float* __restrict__ A, const float* __restrict__ W,
                               float* __restrict__ C, int N) {
    extern __shared__ float sm[];
    float* Ws = sm;              // 128*128
    float* As = sm + 128 * 128;  // 64*128

    const int tid = threadIdx.x;

    // Load W (4096 float4)
    {
        const float4* W4 = (const float4*)W;
        float4* Ws4 = (float4*)Ws;
        #pragma unroll
        for (int i = 0; i < 16; i++) Ws4[tid + i * 256] = W4[tid + i * 256];
    }
    // Load A tile (64 rows x 32 float4)
    const int rowBase = blockIdx.x * 64;
    {
        const float4* A4 = (const float4*)A;
        float4* As4 = (float4*)As;
        #pragma unroll
        for (int i = 0; i < 8; i++) {
            int idx = tid + i * 256;
            int r = idx >> 5;
            int c4 = idx & 31;
            float4 v;
            if (rowBase + r < N) {
                v = A4[(size_t)(rowBase + r) * 32 + c4];
                if (RELU) {
                    v.x = fmaxf(v.x, 0.f); v.y = fmaxf(v.y, 0.f);
                    v.z = fmaxf(v.z, 0.f); v.w = fmaxf(v.w, 0.f);
                }
            } else {
                v = make_float4(0.f, 0.f, 0.f, 0.f);
            }
            As4[idx] = v;
        }
    }
    __syncthreads();

    const int lane = tid & 31;
    const int warp = tid >> 5;

    unsigned long long acc2[8][2];
    #pragma unroll
    for (int r = 0; r < 8; r++) { acc2[r][0] = 0ull; acc2[r][1] = 0ull; }

    for (int k = 0; k < 128; k += 4) {
        float4 a[8];
        #pragma unroll
        for (int r = 0; r < 8; r++)
            a[r] = *(const float4*)(As + (warp * 8 + r) * 128 + k);

        unsigned long long wlo[4], whi[4];
        #pragma unroll
        for (int kk = 0; kk < 4; kk++) {
            const unsigned long long* wp =
                (const unsigned long long*)(Ws + (k + kk) * 128 + lane * 4);
            wlo[kk] = wp[0];
            whi[kk] = wp[1];
        }

        #pragma unroll
        for (int kk = 0; kk < 4; kk++) {
            #pragma unroll
            for (int r = 0; r < 8; r++) {
                float av = (kk == 0) ? a[r].x : (kk == 1) ? a[r].y
                         : (kk == 2) ? a[r].z : a[r].w;
                unsigned long long av2 = pack2(av, av);
                FMA2(acc2[r][0], av2, wlo[kk]);
                FMA2(acc2[r][1], av2, whi[kk]);
            }
        }
    }

    #pragma unroll
    for (int r = 0; r < 8; r++) {
        int row = rowBase + warp * 8 + r;
        if (row < N) {
            float4 o;
            unpack2(o.x, o.y, acc2[r][0]);
            unpack2(o.z, o.w, acc2[r][1]);
            *(float4*)(C + (size_t)row * 128 + lane * 4) = o;
        }
    }
}

// ---------------------------------------------------------------------------
// GEMM: C[N,40] = relu(A[N,128]) @ W[128,40] — f32x2, one row per thread.
// ---------------------------------------------------------------------------
__global__ void gemm40_kernel(const float* __restrict__ A, const float* __restrict__ W,
                              float* __restrict__ C, int N) {
    __shared__ float Ws[128 * 40];
    for (int i = threadIdx.x; i < 128 * 40; i += blockDim.x) Ws[i] = W[i];
    __syncthreads();

    int row = blockIdx.x * blockDim.x + threadIdx.x;
    if (row >= N) return;

    unsigned long long acc2[20];
    #pragma unroll
    for (int j = 0; j < 20; j++) acc2[j] = 0ull;

    const float4* Arow = (const float4*)(A + (size_t)row * 128);
    for (int k4 = 0; k4 < 32; k4++) {
        float4 a = Arow[k4];
        a.x = fmaxf(a.x, 0.f); a.y = fmaxf(a.y, 0.f);
        a.z = fmaxf(a.z, 0.f); a.w = fmaxf(a.w, 0.f);
        #pragma unroll
        for (int kk = 0; kk < 4; kk++) {
            float av = (kk == 0) ? a.x : (kk == 1) ? a.y : (kk == 2) ? a.z : a.w;
            unsigned long long av2 = pack2(av, av);
            const unsigned long long* wrow =
                (const unsigned long long*)(Ws + (k4 * 4 + kk) * 40);
            #pragma unroll
            for (int j = 0; j < 20; j++) FMA2(acc2[j], av2, wrow[j]);
        }
    }

    unsigned long long* Co = (unsigned long long*)(C + (size_t)row * 40);
    #pragma unroll
    for (int j = 0; j < 20; j++) Co[j] = acc2[j];
}

// ---------------------------------------------------------------------------
// CSR gather (128 dims): one warp per node, lane owns 4 cols.
// agg[n] = b + sum_{e in csr[n]} hw[src[e]]   (bias init fused)
// ---------------------------------------------------------------------------
__global__ void gather128_kernel(const float* __restrict__ hw,
                                 const float* __restrict__ b,
                                 float* __restrict__ agg) {
    int w = (blockIdx.x * blockDim.x + threadIdx.x) >> 5;
    int lane = threadIdx.x & 31;
    if (w >= NUM_NODES) return;
    int beg = __ldg(&g_off[w]);
    int end = __ldg(&g_off[w + 1]);

    float4 acc = *(const float4*)(b + lane * 4);
    int i = beg;
    for (; i + 4 <= end; i += 4) {
        int s0 = g_csrc[i], s1 = g_csrc[i + 1], s2 = g_csrc[i + 2], s3 = g_csrc[i + 3];
        float4 v0 = *(const float4*)(hw + (size_t)s0 * 128 + lane * 4);
        float4 v1 = *(const float4*)(hw + (size_t)s1 * 128 + lane * 4);
        float4 v2 = *(const float4*)(hw + (size_t)s2 * 128 + lane * 4);
        float4 v3 = *(const float4*)(hw + (size_t)s3 * 128 + lane * 4);
        acc.x += v0.x + v1.x + v2.x + v3.x;
        acc.y += v0.y + v1.y + v2.y + v3.y;
        acc.z += v0.z + v1.z + v2.z + v3.z;
        acc.w += v0.w + v1.w + v2.w + v3.w;
    }
    for (; i < end; i++) {
        int s = g_csrc[i];
        float4 v = *(const float4*)(hw + (size_t)s * 128 + lane * 4);
        acc.x += v.x; acc.y += v.y; acc.z += v.z; acc.w += v.w;
    }
    *(float4*)(agg + (size_t)w * 128 + lane * 4) = acc;
}

// ---------------------------------------------------------------------------
// CSR gather (40 dims): one warp per node, lanes 0..9 own a float4 each.
// ---------------------------------------------------------------------------
__global__ void gather40_kernel(const float* __restrict__ hw,
                                const float* __restrict__ b,
                                float* __restrict__ out) {
    int w = (blockIdx.x * blockDim.x + threadIdx.x) >> 5;
    int lane = threadIdx.x & 31;
    if (w >= NUM_NODES) return;
    int beg = __ldg(&g_off[w]);
    int end = __ldg(&g_off[w + 1]);

    float4 acc = make_float4(0.f, 0.f, 0.f, 0.f);
    if (lane < 10) acc = *(const float4*)(b + lane * 4);
    int i = beg;
    for (; i + 2 <= end; i += 2) {
        int s0 = g_csrc[i], s1 = g_csrc[i + 1];
        if (lane < 10) {
            float4 v0 = *(const float4*)(hw + (size_t)s0 * 40 + lane * 4);
            float4 v1 = *(const float4*)(hw + (size_t)s1 * 40 + lane * 4);
            acc.x += v0.x + v1.x; acc.y += v0.y + v1.y;
            acc.z += v0.z + v1.z; acc.w += v0.w + v1.w;
        }
    }
    for (; i < end; i++) {
        int s = g_csrc[i];
        if (lane < 10) {
            float4 v = *(const float4*)(hw + (size_t)s * 40 + lane * 4);
            acc.x += v.x; acc.y += v.y; acc.z += v.z; acc.w += v.w;
        }
    }
    if (lane < 10)
        *(float4*)(out + (size_t)w * 40 + lane * 4) = acc;
}

// ---------------------------------------------------------------------------
// Launch — CSR build forked onto a side stream, overlapped with layer-0 GEMM.
// Stream/events created once on the first (non-captured correctness) call;
// identical work is enqueued on every call, so determinism holds.
// ---------------------------------------------------------------------------
extern "C" void kernel_launch(void* const* d_in, const int* in_sizes, int n_in,
                              void* d_out, int out_size) {
    const float* x  = (const float*)d_in[0];
    const int*   ei = (const int*)d_in[1];
    const float* W0 = (const float*)d_in[2];
    const float* b0 = (const float*)d_in[3];
    const float* W1 = (const float*)d_in[4];
    const float* b1 = (const float*)d_in[5];
    const float* W2 = (const float*)d_in[6];
    const float* b2 = (const float*)d_in[7];
    float* out = (float*)d_out;

    const int N = NUM_NODES, E = NUM_EDGES;

    float *bufHW, *bufAGG;
    cudaGetSymbolAddress((void**)&bufHW, g_bufHW);
    cudaGetSymbolAddress((void**)&bufAGG, g_bufAGG);
    int* degPtr;
    cudaGetSymbolAddress((void**)&degPtr, g_deg);

    const int SMEM = (128 * 128 + 64 * 128) * sizeof(float);  // 96KB
    cudaFuncSetAttribute(gemm128_kernel<false>, cudaFuncAttributeMaxDynamicSharedMemorySize, SMEM);
    cudaFuncSetAttribute(gemm128_kernel<true>,  cudaFuncAttributeMaxDynamicSharedMemorySize, SMEM);

    static cudaStream_t sideStream = nullptr;
    static cudaEvent_t evFork = nullptr, evJoin = nullptr;
    if (sideStream == nullptr) {
        cudaStreamCreateWithFlags(&sideStream, cudaStreamNonBlocking);
        cudaEventCreateWithFlags(&evFork, cudaEventDisableTiming);
        cudaEventCreateWithFlags(&evJoin, cudaEventDisableTiming);
    }

    // --- fork: CSR build on side stream, layer-0 GEMM on main stream ---
    cudaEventRecord(evFork, 0);
    cudaStreamWaitEvent(sideStream, evFork, 0);

    detect_idx_dtype<<<1, 32, 0, sideStream>>>(ei);
    cudaMemsetAsync(degPtr, 0, NUM_NODES * sizeof(int), sideStream);
    hist_kernel<<<(E + 255) / 256, 256, 0, sideStream>>>(ei, E);
    scanA_kernel<<<SCAN_NBLOCKS, SCAN_BLK, 0, sideStream>>>();
    scanB_kernel<<<1, 128, 0, sideStream>>>();
    scanC_kernel<<<(N + 255) / 256, 256, 0, sideStream>>>();
    fill_kernel<<<(E + 255) / 256, 256, 0, sideStream>>>(ei, E);
    cudaEventRecord(evJoin, sideStream);

    // Layer-0 GEMM concurrently on the main stream (depends only on x, W0)
    gemm128_kernel<false><<<(N + 63) / 64, 256, SMEM>>>(x, W0, bufHW, N);

    // --- join: gather needs both the CSR and the layer-0 projections ---
    cudaStreamWaitEvent(0, evJoin, 0);

    const int GWARP_BLOCKS = (N * 32 + 255) / 256;  // 1 warp per node

    gather128_kernel<<<GWARP_BLOCKS, 256>>>(bufHW, b0, bufAGG);

    // Layer 1
    gemm128_kernel<true><<<(N + 63) / 64, 256, SMEM>>>(bufAGG, W1, bufHW, N);
    gather128_kernel<<<GWARP_BLOCKS, 256>>>(bufHW, b1, bufAGG);

    // Layer 2
    gemm40_kernel<<<(N + 255) / 256, 256>>>(bufAGG, W2, bufHW, N);
    gather40_kernel<<<GWARP_BLOCKS, 256>>>(bufHW, b2, out);
}